// round 1
// baseline (speedup 1.0000x reference)
#include <cuda_runtime.h>

#define IN_DIM  4096
#define OUT_DIM 4096
#define RANK    16
#define NSUB    4
#define RTOT    80          // 5 adapters * rank 16
#define NW      84          // 80 down-proj rows + 4 gate rows
#define NWPAD   88
#define SCALING 2.0f        // ALPHA / RANK = 32/16

// scratch: per-token gated+scaled rank coefficients c[M][80]
__device__ float g_c[8192 * RTOT];

// ---------------------------------------------------------------------------
// Kernel A: c[tok, r] = SCALING * gate * (x . A_r)
// Skinny GEMM [M,4096] x [4096,84] with 128-token tiles; gates fused in smem.
// ---------------------------------------------------------------------------
__global__ __launch_bounds__(256) void lora_prep_kernel(
    const float* __restrict__ x,
    const float* __restrict__ base_A,     // [16, 4096]
    const float* __restrict__ sub_wgate,  // [4, 4096]
    const float* __restrict__ sub_A)      // [4, 16, 4096] == [64, 4096]
{
    // one shared buffer, two lifetimes:
    //   during K loop:  As = sh[0 .. 16*128), Ws = sh[16*128 .. 16*128+16*88)
    //   after K loop :  dots[128][88]
    __shared__ float sh[128 * NWPAD];   // 11264 floats = 44 KB
    float* As = sh;                     // [16][128] (k-major, token inner)
    float* Ws = sh + 16 * 128;          // [16][88]

    const int tid = threadIdx.x;
    const int m0  = blockIdx.x * 128;
    const int ty  = tid >> 4;           // 0..15  -> 8 tokens each
    const int tx  = tid & 15;           // 0..15  -> 6 outputs each

    float acc[8][6];
    #pragma unroll
    for (int i = 0; i < 8; ++i)
        #pragma unroll
        for (int j = 0; j < 6; ++j) acc[i][j] = 0.f;

    const int ar = tid >> 2;            // 0..63
    const int ac = (tid & 3) * 4;       // 0,4,8,12

    for (int k0 = 0; k0 < IN_DIM; k0 += 16) {
        // --- load x tile, transposed into As[k][m] ---
        #pragma unroll
        for (int h = 0; h < 2; ++h) {
            int ml = ar + h * 64;
            float4 v = *(const float4*)&x[(size_t)(m0 + ml) * IN_DIM + k0 + ac];
            As[(ac + 0) * 128 + ml] = v.x;
            As[(ac + 1) * 128 + ml] = v.y;
            As[(ac + 2) * 128 + ml] = v.z;
            As[(ac + 3) * 128 + ml] = v.w;
        }
        // --- load 84 weight rows (A rows + gate rows), pad to 88 ---
        #pragma unroll
        for (int it = 0; it < 6; ++it) {
            int id = tid + it * 256;
            if (id < NWPAD * 16) {
                int col = id >> 4;
                int k   = id & 15;
                float v = 0.f;
                if (col < 16)      v = base_A[col * IN_DIM + k0 + k];
                else if (col < 80) v = sub_A[(col - 16) * IN_DIM + k0 + k];
                else if (col < NW) v = sub_wgate[(col - 80) * IN_DIM + k0 + k];
                Ws[k * NWPAD + col] = v;
            }
        }
        __syncthreads();

        #pragma unroll
        for (int k = 0; k < 16; ++k) {
            float a[8], w[6];
            #pragma unroll
            for (int i = 0; i < 8; ++i) a[i] = As[k * 128 + ty * 8 + i];
            #pragma unroll
            for (int j = 0; j < 6; ++j) {
                int col = tx * 6 + j;
                w[j] = (col < NWPAD) ? Ws[k * NWPAD + col] : 0.f;
            }
            #pragma unroll
            for (int i = 0; i < 8; ++i)
                #pragma unroll
                for (int j = 0; j < 6; ++j)
                    acc[i][j] = fmaf(a[i], w[j], acc[i][j]);
        }
        __syncthreads();
    }

    // --- dump raw dots to smem: dots[tok][col], col 80..83 are gates ---
    #pragma unroll
    for (int i = 0; i < 8; ++i) {
        int tok = ty * 8 + i;
        #pragma unroll
        for (int j = 0; j < 6; ++j) {
            int col = tx * 6 + j;
            if (col < NWPAD) sh[tok * NWPAD + col] = acc[i][j];
        }
    }
    __syncthreads();

    // --- combine: fold SCALING and ReLU gate, write c ---
    for (int e = tid; e < 128 * RTOT; e += 256) {
        int tok = e / RTOT;
        int r   = e - tok * RTOT;
        float f = 1.f;
        if (r >= 16) {
            float g = sh[tok * NWPAD + 80 + ((r - 16) >> 4)];
            f = g > 0.f ? g : 0.f;
        }
        g_c[(size_t)(m0 + tok) * RTOT + r] = SCALING * sh[tok * NWPAD + r] * f;
    }
}

// ---------------------------------------------------------------------------
// Kernel B: out[m,n] = bias[n] + sum_k x[m,k] W[n,k] + sum_r c[m,r] Bcat[n,r]
// Fused as one K = 4096 + 80 GEMM. 128x128 tile, BK=16, 8x8 micro-tile.
// ---------------------------------------------------------------------------
__global__ __launch_bounds__(256) void lora_main_kernel(
    const float* __restrict__ x,
    const float* __restrict__ W,        // [OUT, IN]
    const float* __restrict__ bias,     // [OUT]
    const float* __restrict__ base_B,   // [OUT, 16]
    const float* __restrict__ sub_B,    // [4, OUT, 16]
    float* __restrict__ out)
{
    __shared__ float As[16][128];
    __shared__ float Bs[16][128];

    const int tid = threadIdx.x;
    const int bn  = blockIdx.x * 128;
    const int bm  = blockIdx.y * 128;
    const int ty  = tid >> 4;
    const int tx  = tid & 15;

    float acc[8][8];
    #pragma unroll
    for (int i = 0; i < 8; ++i)
        #pragma unroll
        for (int j = 0; j < 8; ++j) acc[i][j] = 0.f;

    const int lr = tid >> 2;            // 0..63
    const int lc = (tid & 3) * 4;       // 0,4,8,12

    const int NKT = IN_DIM / 16 + RTOT / 16;   // 256 + 5 = 261

    for (int kt = 0; kt < NKT; ++kt) {
        const int k0 = kt * 16;

        // --- As: x (main) or c (rank tail) ---
        #pragma unroll
        for (int h = 0; h < 2; ++h) {
            int ml = lr + h * 64;
            int m  = bm + ml;
            float4 v;
            if (kt < IN_DIM / 16)
                v = *(const float4*)&x[(size_t)m * IN_DIM + k0 + lc];
            else
                v = *(const float4*)&g_c[(size_t)m * RTOT + (k0 - IN_DIM) + lc];
            As[lc + 0][ml] = v.x;
            As[lc + 1][ml] = v.y;
            As[lc + 2][ml] = v.z;
            As[lc + 3][ml] = v.w;
        }
        // --- Bs: W (main) or Bcat (rank tail) ---
        #pragma unroll
        for (int h = 0; h < 2; ++h) {
            int nl = lr + h * 64;
            int n  = bn + nl;
            float4 v;
            if (kt < IN_DIM / 16) {
                v = *(const float4*)&W[(size_t)n * IN_DIM + k0 + lc];
            } else {
                int kk = k0 - IN_DIM + lc;        // 0..76, multiple of 4
                if (kk < 16) {
                    v = *(const float4*)&base_B[(size_t)n * RANK + kk];
                } else {
                    int j  = (kk - 16) >> 4;
                    int rr = (kk - 16) & 15;
                    v = *(const float4*)&sub_B[((size_t)j * OUT_DIM + n) * RANK + rr];
                }
            }
            Bs[lc + 0][nl] = v.x;
            Bs[lc + 1][nl] = v.y;
            Bs[lc + 2][nl] = v.z;
            Bs[lc + 3][nl] = v.w;
        }
        __syncthreads();

        #pragma unroll
        for (int k = 0; k < 16; ++k) {
            float4 a0 = *(const float4*)&As[k][ty * 8];
            float4 a1 = *(const float4*)&As[k][ty * 8 + 4];
            float4 b0 = *(const float4*)&Bs[k][tx * 8];
            float4 b1 = *(const float4*)&Bs[k][tx * 8 + 4];
            float a[8] = {a0.x, a0.y, a0.z, a0.w, a1.x, a1.y, a1.z, a1.w};
            float b[8] = {b0.x, b0.y, b0.z, b0.w, b1.x, b1.y, b1.z, b1.w};
            #pragma unroll
            for (int i = 0; i < 8; ++i)
                #pragma unroll
                for (int j = 0; j < 8; ++j)
                    acc[i][j] = fmaf(a[i], b[j], acc[i][j]);
        }
        __syncthreads();
    }

    // --- epilogue: add bias, store ---
    float bv[8];
    #pragma unroll
    for (int j = 0; j < 8; ++j) bv[j] = __ldg(&bias[bn + tx * 8 + j]);

    #pragma unroll
    for (int i = 0; i < 8; ++i) {
        int m = bm + ty * 8 + i;
        int n = bn + tx * 8;
        float4 o0, o1;
        o0.x = acc[i][0] + bv[0];
        o0.y = acc[i][1] + bv[1];
        o0.z = acc[i][2] + bv[2];
        o0.w = acc[i][3] + bv[3];
        o1.x = acc[i][4] + bv[4];
        o1.y = acc[i][5] + bv[5];
        o1.z = acc[i][6] + bv[6];
        o1.w = acc[i][7] + bv[7];
        *(float4*)&out[(size_t)m * OUT_DIM + n]     = o0;
        *(float4*)&out[(size_t)m * OUT_DIM + n + 4] = o1;
    }
}

// ---------------------------------------------------------------------------
extern "C" void kernel_launch(void* const* d_in, const int* in_sizes, int n_in,
                              void* d_out, int out_size)
{
    const float* x         = (const float*)d_in[0];
    const float* base_W    = (const float*)d_in[1];
    const float* base_b    = (const float*)d_in[2];
    const float* base_A    = (const float*)d_in[3];
    const float* base_B    = (const float*)d_in[4];
    const float* sub_wgate = (const float*)d_in[5];
    const float* sub_A     = (const float*)d_in[6];
    const float* sub_B     = (const float*)d_in[7];
    float* out = (float*)d_out;

    const int M = in_sizes[0] / IN_DIM;   // 8192 tokens

    lora_prep_kernel<<<M / 128, 256>>>(x, base_A, sub_wgate, sub_A);

    dim3 grid(OUT_DIM / 128, M / 128);
    lora_main_kernel<<<grid, 256>>>(x, base_W, base_b, base_B, sub_B, out);
}

// round 3
// speedup vs baseline: 5.4303x; 5.4303x over previous
#include <cuda_runtime.h>
#include <cuda_fp16.h>
#include <cstdint>

#define IN_DIM  4096
#define OUT_DIM 4096
#define RANK    16
#define RTOT    80          // 5 adapters * rank 16
#define NW      84
#define NWPAD   88
#define SCALING 2.0f        // ALPHA / RANK

#define MTOK    8192
#define KPAD    4224        // 4096 + 80, padded to 66*64
#define BK      64
#define NKT     (KPAD / BK) // 66

#define ASTAGE      16384                 // 128 rows * 128 B
#define STAGE_BYTES 32768                 // A + B
#define SMEM_DYN    (3 * STAGE_BYTES)     // 98304

// ---------------- scratch (device globals: no runtime alloc allowed) -------
__device__ float g_c[(size_t)MTOK * RTOT];
__device__ __align__(16) __half g_a16[(size_t)MTOK   * KPAD];
__device__ __align__(16) __half g_b16[(size_t)OUT_DIM * KPAD];

// ---------------- PTX helpers (base-target only: no 'a' features) ----------
__device__ __forceinline__ uint32_t smem_u32(const void* p) {
    uint32_t a;
    asm("{ .reg .u64 t; cvta.to.shared.u64 t, %1; cvt.u32.u64 %0, t; }" : "=r"(a) : "l"(p));
    return a;
}
__device__ __forceinline__ void cp16(uint32_t dst, const void* src) {
    asm volatile("cp.async.cg.shared.global [%0], [%1], 16;" :: "r"(dst), "l"(src));
}
__device__ __forceinline__ void cp_commit() {
    asm volatile("cp.async.commit_group;" ::: "memory");
}
__device__ __forceinline__ void cp_wait1() {
    asm volatile("cp.async.wait_group 1;" ::: "memory");
}
__device__ __forceinline__ void ldsm4(uint32_t* r, uint32_t addr) {
    asm volatile("ldmatrix.sync.aligned.m8n8.x4.shared.b16 {%0,%1,%2,%3}, [%4];"
                 : "=r"(r[0]), "=r"(r[1]), "=r"(r[2]), "=r"(r[3]) : "r"(addr));
}
__device__ __forceinline__ void mma16816(float* d, const uint32_t* a, const uint32_t* b) {
    asm volatile(
        "mma.sync.aligned.m16n8k16.row.col.f32.f16.f16.f32 "
        "{%0,%1,%2,%3}, {%4,%5,%6,%7}, {%8,%9}, {%0,%1,%2,%3};"
        : "+f"(d[0]), "+f"(d[1]), "+f"(d[2]), "+f"(d[3])
        : "r"(a[0]), "r"(a[1]), "r"(a[2]), "r"(a[3]), "r"(b[0]), "r"(b[1]));
}

// ---------------------------------------------------------------------------
// Kernel A: c[tok, r] = SCALING * gate * (x . A_r)   (fp32, proven in R1)
// ---------------------------------------------------------------------------
__global__ __launch_bounds__(256) void lora_prep_kernel(
    const float* __restrict__ x,
    const float* __restrict__ base_A,
    const float* __restrict__ sub_wgate,
    const float* __restrict__ sub_A)
{
    __shared__ float sh[128 * NWPAD];
    float* As = sh;
    float* Ws = sh + 16 * 128;

    const int tid = threadIdx.x;
    const int m0  = blockIdx.x * 128;
    const int ty  = tid >> 4;
    const int tx  = tid & 15;

    float acc[8][6];
    #pragma unroll
    for (int i = 0; i < 8; ++i)
        #pragma unroll
        for (int j = 0; j < 6; ++j) acc[i][j] = 0.f;

    const int ar = tid >> 2;
    const int ac = (tid & 3) * 4;

    for (int k0 = 0; k0 < IN_DIM; k0 += 16) {
        #pragma unroll
        for (int h = 0; h < 2; ++h) {
            int ml = ar + h * 64;
            float4 v = *(const float4*)&x[(size_t)(m0 + ml) * IN_DIM + k0 + ac];
            As[(ac + 0) * 128 + ml] = v.x;
            As[(ac + 1) * 128 + ml] = v.y;
            As[(ac + 2) * 128 + ml] = v.z;
            As[(ac + 3) * 128 + ml] = v.w;
        }
        #pragma unroll
        for (int it = 0; it < 6; ++it) {
            int id = tid + it * 256;
            if (id < NWPAD * 16) {
                int col = id >> 4;
                int k   = id & 15;
                float v = 0.f;
                if (col < 16)      v = base_A[col * IN_DIM + k0 + k];
                else if (col < 80) v = sub_A[(col - 16) * IN_DIM + k0 + k];
                else if (col < NW) v = sub_wgate[(col - 80) * IN_DIM + k0 + k];
                Ws[k * NWPAD + col] = v;
            }
        }
        __syncthreads();

        #pragma unroll
        for (int k = 0; k < 16; ++k) {
            float a[8], w[6];
            #pragma unroll
            for (int i = 0; i < 8; ++i) a[i] = As[k * 128 + ty * 8 + i];
            #pragma unroll
            for (int j = 0; j < 6; ++j) {
                int col = tx * 6 + j;
                w[j] = (col < NWPAD) ? Ws[k * NWPAD + col] : 0.f;
            }
            #pragma unroll
            for (int i = 0; i < 8; ++i)
                #pragma unroll
                for (int j = 0; j < 6; ++j)
                    acc[i][j] = fmaf(a[i], w[j], acc[i][j]);
        }
        __syncthreads();
    }

    #pragma unroll
    for (int i = 0; i < 8; ++i) {
        int tok = ty * 8 + i;
        #pragma unroll
        for (int j = 0; j < 6; ++j) {
            int col = tx * 6 + j;
            if (col < NWPAD) sh[tok * NWPAD + col] = acc[i][j];
        }
    }
    __syncthreads();

    for (int e = tid; e < 128 * RTOT; e += 256) {
        int tok = e / RTOT;
        int r   = e - tok * RTOT;
        float f = 1.f;
        if (r >= 16) {
            float g = sh[tok * NWPAD + 80 + ((r - 16) >> 4)];
            f = g > 0.f ? g : 0.f;
        }
        g_c[(size_t)(m0 + tok) * RTOT + r] = SCALING * sh[tok * NWPAD + r] * f;
    }
}

// ---------------------------------------------------------------------------
// fp32 -> fp16 conversion into row-major [*, KPAD] scratch
// ---------------------------------------------------------------------------
__device__ __forceinline__ uint4 pack8_h(const float* v) {
    __half2 h01 = __floats2half2_rn(v[0], v[1]);
    __half2 h23 = __floats2half2_rn(v[2], v[3]);
    __half2 h45 = __floats2half2_rn(v[4], v[5]);
    __half2 h67 = __floats2half2_rn(v[6], v[7]);
    uint4 u;
    u.x = *reinterpret_cast<uint32_t*>(&h01);
    u.y = *reinterpret_cast<uint32_t*>(&h23);
    u.z = *reinterpret_cast<uint32_t*>(&h45);
    u.w = *reinterpret_cast<uint32_t*>(&h67);
    return u;
}

__global__ __launch_bounds__(256) void conv_a_kernel(const float* __restrict__ x)
{
    int id = blockIdx.x * 256 + threadIdx.x;
    int m  = id / (KPAD / 8);
    int k  = (id % (KPAD / 8)) * 8;

    float v[8];
    if (k < IN_DIM) {
        float4 v0 = *(const float4*)&x[(size_t)m * IN_DIM + k];
        float4 v1 = *(const float4*)&x[(size_t)m * IN_DIM + k + 4];
        v[0]=v0.x; v[1]=v0.y; v[2]=v0.z; v[3]=v0.w;
        v[4]=v1.x; v[5]=v1.y; v[6]=v1.z; v[7]=v1.w;
    } else if (k < IN_DIM + RTOT) {
        float4 v0 = *(const float4*)&g_c[(size_t)m * RTOT + (k - IN_DIM)];
        float4 v1 = *(const float4*)&g_c[(size_t)m * RTOT + (k - IN_DIM) + 4];
        v[0]=v0.x; v[1]=v0.y; v[2]=v0.z; v[3]=v0.w;
        v[4]=v1.x; v[5]=v1.y; v[6]=v1.z; v[7]=v1.w;
    } else {
        #pragma unroll
        for (int q = 0; q < 8; ++q) v[q] = 0.f;
    }
    *(uint4*)&g_a16[(size_t)m * KPAD + k] = pack8_h(v);
}

__global__ __launch_bounds__(256) void conv_b_kernel(
    const float* __restrict__ W,
    const float* __restrict__ base_B,
    const float* __restrict__ sub_B)
{
    int id = blockIdx.x * 256 + threadIdx.x;
    int n  = id / (KPAD / 8);
    int k  = (id % (KPAD / 8)) * 8;

    const float* src = nullptr;
    if (k < IN_DIM) {
        src = &W[(size_t)n * IN_DIM + k];
    } else if (k < IN_DIM + RANK) {
        src = &base_B[(size_t)n * RANK + (k - IN_DIM)];
    } else if (k < IN_DIM + RTOT) {
        int kk = k - IN_DIM - RANK;
        int j  = kk >> 4;
        int rr = kk & 15;
        src = &sub_B[((size_t)j * OUT_DIM + n) * RANK + rr];
    }

    float v[8];
    if (src) {
        float4 v0 = *(const float4*)src;
        float4 v1 = *(const float4*)(src + 4);
        v[0]=v0.x; v[1]=v0.y; v[2]=v0.z; v[3]=v0.w;
        v[4]=v1.x; v[5]=v1.y; v[6]=v1.z; v[7]=v1.w;
    } else {
        #pragma unroll
        for (int q = 0; q < 8; ++q) v[q] = 0.f;
    }
    *(uint4*)&g_b16[(size_t)n * KPAD + k] = pack8_h(v);
}

// ---------------------------------------------------------------------------
// HMMA GEMM: out[8192,4096] = A16[8192,KPAD] * B16[4096,KPAD]^T + bias
// 128x128 CTA tile, BK=64, 3-stage cp.async pipeline, 8 warps (64x32 each).
// ---------------------------------------------------------------------------
__global__ __launch_bounds__(256, 2) void lora_gemm_hmma(
    const float* __restrict__ bias,
    float* __restrict__ out)
{
    extern __shared__ __align__(1024) char smem[];
    const uint32_t sb = smem_u32(smem);

    const int tid  = threadIdx.x;
    const int lane = tid & 31;
    const int wid  = tid >> 5;
    const int bm   = blockIdx.y * 128;
    const int bn   = blockIdx.x * 128;
    const int wm   = (wid & 1) * 64;    // warp M offset in tile
    const int wn   = (wid >> 1) * 32;   // warp N offset in tile

    float acc[4][4][4];
    #pragma unroll
    for (int mi = 0; mi < 4; ++mi)
        #pragma unroll
        for (int ni = 0; ni < 4; ++ni)
            #pragma unroll
            for (int q = 0; q < 4; ++q) acc[mi][ni][q] = 0.f;

    const char* gA = (const char*)(g_a16 + (size_t)bm * KPAD);
    const char* gB = (const char*)(g_b16 + (size_t)bn * KPAD);
    const size_t rowbytes = (size_t)KPAD * 2;

    // cp.async mapping: 4 x 16B chunks per thread per operand per stage
    const int crow = tid >> 3;             // base row (0..31), +32*i
    const int ccol = (tid & 7) * 16;       // byte col within 128B row

    // ldmatrix address components (swizzle XOR pattern constant per thread)
    const int arow  = wm + (lane & 15);
    const int akoff = (lane >> 4) * 16;
    const int apx   = (arow & 7) << 4;
    const int bmat  = lane >> 3;
    const int brow  = wn + (bmat >> 1) * 8 + (lane & 7);
    const int bkoff = (bmat & 1) * 16;
    const int bpx   = (brow & 7) << 4;

#define LOAD_STAGE(s, kt)                                                      \
    {                                                                          \
        const int kb = (kt) * (BK * 2);                                        \
        _Pragma("unroll")                                                      \
        for (int i = 0; i < 4; ++i) {                                          \
            int row = crow + i * 32;                                           \
            uint32_t off = row * 128 + ccol;                                   \
            uint32_t sw  = off ^ ((off >> 3) & 0x70);                          \
            cp16(sb + (s) * STAGE_BYTES + sw, gA + (size_t)row * rowbytes + kb + ccol); \
            cp16(sb + (s) * STAGE_BYTES + ASTAGE + sw,                         \
                 gB + (size_t)row * rowbytes + kb + ccol);                     \
        }                                                                      \
        cp_commit();                                                           \
    }

    LOAD_STAGE(0, 0);
    LOAD_STAGE(1, 1);

    for (int kt = 0; kt < NKT; ++kt) {
        cp_wait1();
        __syncthreads();
        if (kt + 2 < NKT) {
            const int s2 = (kt + 2) % 3;
            LOAD_STAGE(s2, kt + 2);
        } else {
            cp_commit();   // empty group keeps wait_group(1) semantics correct
        }

        const uint32_t sa = sb + (kt % 3) * STAGE_BYTES;
        const uint32_t sB = sa + ASTAGE;

        #pragma unroll
        for (int ks = 0; ks < 4; ++ks) {
            const int kb = ks * 32;
            uint32_t a[4][4], b[2][4];
            #pragma unroll
            for (int mi = 0; mi < 4; ++mi)
                ldsm4(a[mi], sa + (uint32_t)(arow + mi * 16) * 128 +
                             (uint32_t)((kb + akoff) ^ apx));
            #pragma unroll
            for (int g = 0; g < 2; ++g)
                ldsm4(b[g], sB + (uint32_t)(brow + g * 16) * 128 +
                            (uint32_t)((kb + bkoff) ^ bpx));
            #pragma unroll
            for (int mi = 0; mi < 4; ++mi) {
                mma16816(acc[mi][0], a[mi], &b[0][0]);
                mma16816(acc[mi][1], a[mi], &b[0][2]);
                mma16816(acc[mi][2], a[mi], &b[1][0]);
                mma16816(acc[mi][3], a[mi], &b[1][2]);
            }
        }
    }
#undef LOAD_STAGE

    // epilogue: D fragment (g = lane/4 row, t4 = lane%4 -> 2 consecutive n)
    const int g  = lane >> 2;
    const int t4 = lane & 3;
    #pragma unroll
    for (int ni = 0; ni < 4; ++ni) {
        const int n = bn + wn + ni * 8 + t4 * 2;
        const float2 bv = *(const float2*)&bias[n];
        #pragma unroll
        for (int mi = 0; mi < 4; ++mi) {
            const int m = bm + wm + mi * 16 + g;
            float2 o0, o1;
            o0.x = acc[mi][ni][0] + bv.x;
            o0.y = acc[mi][ni][1] + bv.y;
            o1.x = acc[mi][ni][2] + bv.x;
            o1.y = acc[mi][ni][3] + bv.y;
            *(float2*)&out[(size_t)m * OUT_DIM + n]       = o0;
            *(float2*)&out[(size_t)(m + 8) * OUT_DIM + n] = o1;
        }
    }
}

// ---------------------------------------------------------------------------
extern "C" void kernel_launch(void* const* d_in, const int* in_sizes, int n_in,
                              void* d_out, int out_size)
{
    const float* x         = (const float*)d_in[0];
    const float* base_W    = (const float*)d_in[1];
    const float* base_b    = (const float*)d_in[2];
    const float* base_A    = (const float*)d_in[3];
    const float* base_B    = (const float*)d_in[4];
    const float* sub_wgate = (const float*)d_in[5];
    const float* sub_A     = (const float*)d_in[6];
    const float* sub_B     = (const float*)d_in[7];
    float* out = (float*)d_out;

    const int M = in_sizes[0] / IN_DIM;   // 8192 tokens

    lora_prep_kernel<<<M / 128, 256>>>(x, base_A, sub_wgate, sub_A);

    conv_a_kernel<<<(M * (KPAD / 8)) / 256, 256>>>(x);
    conv_b_kernel<<<(OUT_DIM * (KPAD / 8)) / 256, 256>>>(base_W, base_B, sub_B);

    static int smem_set = 0;
    if (!smem_set) {
        cudaFuncSetAttribute(lora_gemm_hmma,
                             cudaFuncAttributeMaxDynamicSharedMemorySize, SMEM_DYN);
        smem_set = 1;
    }
    dim3 grid(OUT_DIM / 128, M / 128);
    lora_gemm_hmma<<<grid, 256, SMEM_DYN>>>(base_b, out);
}

// round 4
// speedup vs baseline: 10.2955x; 1.8959x over previous
#include <cuda_runtime.h>
#include <cuda_fp16.h>
#include <cstdint>

#define IN_DIM  4096
#define OUT_DIM 4096
#define RANK    16
#define RTOT    80          // 5 adapters * rank 16
#define SCALING 2.0f        // ALPHA / RANK

#define MTOK    8192
#define KPAD    4224        // 4096 + 128 tail (80 used + 48 zero pad)
#define BK      64
#define NKT     (KPAD / BK) // 66

#define ASTAGE      16384                 // 128 rows * 128 B
#define STAGE_BYTES 32768                 // A + B
#define SMEM_DYN    (3 * STAGE_BYTES)     // 98304

// prep GEMM staging: A 64 rows, B 128 rows
#define P_ASTAGE 8192
#define P_STAGE  24576
#define P_SMEM   (3 * P_STAGE)            // 73728

// ---------------- scratch (device globals: no runtime alloc allowed) -------
__device__ __align__(16) __half g_a16[(size_t)MTOK    * KPAD];
__device__ __align__(16) __half g_b16[(size_t)OUT_DIM * KPAD];
__device__ __align__(16) __half g_w16[(size_t)128 * IN_DIM];   // prep weights
__device__ __align__(16) float  g_dots[(size_t)MTOK * 128];    // prep output

// ---------------- PTX helpers (base-target only) ----------------------------
__device__ __forceinline__ uint32_t smem_u32(const void* p) {
    uint32_t a;
    asm("{ .reg .u64 t; cvta.to.shared.u64 t, %1; cvt.u32.u64 %0, t; }" : "=r"(a) : "l"(p));
    return a;
}
__device__ __forceinline__ void cp16(uint32_t dst, const void* src) {
    asm volatile("cp.async.cg.shared.global [%0], [%1], 16;" :: "r"(dst), "l"(src));
}
__device__ __forceinline__ void cp_commit() {
    asm volatile("cp.async.commit_group;" ::: "memory");
}
__device__ __forceinline__ void cp_wait1() {
    asm volatile("cp.async.wait_group 1;" ::: "memory");
}
__device__ __forceinline__ void ldsm4(uint32_t* r, uint32_t addr) {
    asm volatile("ldmatrix.sync.aligned.m8n8.x4.shared.b16 {%0,%1,%2,%3}, [%4];"
                 : "=r"(r[0]), "=r"(r[1]), "=r"(r[2]), "=r"(r[3]) : "r"(addr));
}
__device__ __forceinline__ void mma16816(float* d, const uint32_t* a, const uint32_t* b) {
    asm volatile(
        "mma.sync.aligned.m16n8k16.row.col.f32.f16.f16.f32 "
        "{%0,%1,%2,%3}, {%4,%5,%6,%7}, {%8,%9}, {%0,%1,%2,%3};"
        : "+f"(d[0]), "+f"(d[1]), "+f"(d[2]), "+f"(d[3])
        : "r"(a[0]), "r"(a[1]), "r"(a[2]), "r"(a[3]), "r"(b[0]), "r"(b[1]));
}
__device__ __forceinline__ uint4 pack8_h(const float* v) {
    __half2 h01 = __floats2half2_rn(v[0], v[1]);
    __half2 h23 = __floats2half2_rn(v[2], v[3]);
    __half2 h45 = __floats2half2_rn(v[4], v[5]);
    __half2 h67 = __floats2half2_rn(v[6], v[7]);
    uint4 u;
    u.x = *reinterpret_cast<uint32_t*>(&h01);
    u.y = *reinterpret_cast<uint32_t*>(&h23);
    u.z = *reinterpret_cast<uint32_t*>(&h45);
    u.w = *reinterpret_cast<uint32_t*>(&h67);
    return u;
}

// ---------------------------------------------------------------------------
// conv_a: x fp32 -> fp16 main columns of g_a16
// ---------------------------------------------------------------------------
__global__ __launch_bounds__(256) void conv_a_kernel(const float* __restrict__ x)
{
    int id = blockIdx.x * 256 + threadIdx.x;   // MTOK * 512
    int m  = id >> 9;
    int k  = (id & 511) * 8;
    float v[8];
    float4 v0 = *(const float4*)&x[(size_t)m * IN_DIM + k];
    float4 v1 = *(const float4*)&x[(size_t)m * IN_DIM + k + 4];
    v[0]=v0.x; v[1]=v0.y; v[2]=v0.z; v[3]=v0.w;
    v[4]=v1.x; v[5]=v1.y; v[6]=v1.z; v[7]=v1.w;
    *(uint4*)&g_a16[(size_t)m * KPAD + k] = pack8_h(v);
}

// ---------------------------------------------------------------------------
// conv_w: stack [base_A(16) | sub_A(64) | wgate(4) | zero(44)] -> g_w16[128][4096]
// ---------------------------------------------------------------------------
__global__ __launch_bounds__(256) void conv_w_kernel(
    const float* __restrict__ base_A,
    const float* __restrict__ sub_A,
    const float* __restrict__ sub_wgate)
{
    int id  = blockIdx.x * 256 + threadIdx.x;  // 128 * 512
    int row = id >> 9;
    int k   = (id & 511) * 8;

    const float* src = nullptr;
    if (row < 16)      src = &base_A[(size_t)row * IN_DIM + k];
    else if (row < 80) src = &sub_A[(size_t)(row - 16) * IN_DIM + k];
    else if (row < 84) src = &sub_wgate[(size_t)(row - 80) * IN_DIM + k];

    float v[8];
    if (src) {
        float4 v0 = *(const float4*)src;
        float4 v1 = *(const float4*)(src + 4);
        v[0]=v0.x; v[1]=v0.y; v[2]=v0.z; v[3]=v0.w;
        v[4]=v1.x; v[5]=v1.y; v[6]=v1.z; v[7]=v1.w;
    } else {
        #pragma unroll
        for (int q = 0; q < 8; ++q) v[q] = 0.f;
    }
    *(uint4*)&g_w16[(size_t)row * IN_DIM + k] = pack8_h(v);
}

// ---------------------------------------------------------------------------
// conv_b: [W | base_B | sub_B | 0] -> g_b16[4096][KPAD]
// ---------------------------------------------------------------------------
__global__ __launch_bounds__(256) void conv_b_kernel(
    const float* __restrict__ W,
    const float* __restrict__ base_B,
    const float* __restrict__ sub_B)
{
    int id = blockIdx.x * 256 + threadIdx.x;   // OUT_DIM * 528
    int n  = id / (KPAD / 8);
    int k  = (id % (KPAD / 8)) * 8;

    const float* src = nullptr;
    if (k < IN_DIM) {
        src = &W[(size_t)n * IN_DIM + k];
    } else if (k < IN_DIM + RANK) {
        src = &base_B[(size_t)n * RANK + (k - IN_DIM)];
    } else if (k < IN_DIM + RTOT) {
        int kk = k - IN_DIM - RANK;
        int j  = kk >> 4;
        int rr = kk & 15;
        src = &sub_B[((size_t)j * OUT_DIM + n) * RANK + rr];
    }

    float v[8];
    if (src) {
        float4 v0 = *(const float4*)src;
        float4 v1 = *(const float4*)(src + 4);
        v[0]=v0.x; v[1]=v0.y; v[2]=v0.z; v[3]=v0.w;
        v[4]=v1.x; v[5]=v1.y; v[6]=v1.z; v[7]=v1.w;
    } else {
        #pragma unroll
        for (int q = 0; q < 8; ++q) v[q] = 0.f;
    }
    *(uint4*)&g_b16[(size_t)n * KPAD + k] = pack8_h(v);
}

// ---------------------------------------------------------------------------
// prep_hmma: g_dots[8192][128] = A16[:, 0:4096] @ g_w16^T   (HMMA, skinny N)
// BM=64, BN=128, BK=64, 8 warps (32x32 each), 3-stage cp.async pipeline.
// ---------------------------------------------------------------------------
__global__ __launch_bounds__(256, 2) void prep_hmma(void)
{
    extern __shared__ __align__(1024) char smem[];
    const uint32_t sb = smem_u32(smem);

    const int tid  = threadIdx.x;
    const int lane = tid & 31;
    const int wid  = tid >> 5;
    const int bm   = blockIdx.x * 64;
    const int wm   = (wid & 1) * 32;
    const int wn   = (wid >> 1) * 32;

    float acc[2][4][4];
    #pragma unroll
    for (int mi = 0; mi < 2; ++mi)
        #pragma unroll
        for (int ni = 0; ni < 4; ++ni)
            #pragma unroll
            for (int q = 0; q < 4; ++q) acc[mi][ni][q] = 0.f;

    const char* gA = (const char*)(g_a16 + (size_t)bm * KPAD);
    const char* gW = (const char*)g_w16;
    const size_t arow_b = (size_t)KPAD * 2;
    const size_t wrow_b = (size_t)IN_DIM * 2;

    // cp.async maps
    const int a_row = tid >> 2;            // 0..63
    const int a_col = (tid & 3) * 16;      // +i*64
    const int b_row = tid >> 1;            // 0..127
    const int b_col = (tid & 1) * 16;      // +i*32

    const int arow  = wm + (lane & 15);
    const int akoff = (lane >> 4) * 16;
    const int apx   = (arow & 7) << 4;
    const int bmat  = lane >> 3;
    const int brow  = wn + (bmat >> 1) * 8 + (lane & 7);
    const int bkoff = (bmat & 1) * 16;
    const int bpx   = (brow & 7) << 4;

#define P_LOAD(s, kt)                                                          \
    {                                                                          \
        const int kb = (kt) * (BK * 2);                                        \
        _Pragma("unroll")                                                      \
        for (int i = 0; i < 2; ++i) {                                          \
            int cb = a_col + i * 64;                                           \
            uint32_t off = a_row * 128 + cb;                                   \
            uint32_t sw  = off ^ ((off >> 3) & 0x70);                          \
            cp16(sb + (s) * P_STAGE + sw, gA + (size_t)a_row * arow_b + kb + cb); \
        }                                                                      \
        _Pragma("unroll")                                                      \
        for (int i = 0; i < 4; ++i) {                                          \
            int cb = b_col + i * 32;                                           \
            uint32_t off = b_row * 128 + cb;                                   \
            uint32_t sw  = off ^ ((off >> 3) & 0x70);                          \
            cp16(sb + (s) * P_STAGE + P_ASTAGE + sw,                           \
                 gW + (size_t)b_row * wrow_b + kb + cb);                       \
        }                                                                      \
        cp_commit();                                                           \
    }

    P_LOAD(0, 0);
    P_LOAD(1, 1);

    const int PNKT = IN_DIM / BK;   // 64
    for (int kt = 0; kt < PNKT; ++kt) {
        cp_wait1();
        __syncthreads();
        if (kt + 2 < PNKT) {
            P_LOAD((kt + 2) % 3, kt + 2);
        } else {
            cp_commit();
        }

        const uint32_t sa = sb + (kt % 3) * P_STAGE;
        const uint32_t sB = sa + P_ASTAGE;

        #pragma unroll
        for (int ks = 0; ks < 4; ++ks) {
            const int kb = ks * 32;
            uint32_t a[2][4], b[2][4];
            #pragma unroll
            for (int mi = 0; mi < 2; ++mi)
                ldsm4(a[mi], sa + (uint32_t)(arow + mi * 16) * 128 +
                             (uint32_t)((kb + akoff) ^ apx));
            #pragma unroll
            for (int g = 0; g < 2; ++g)
                ldsm4(b[g], sB + (uint32_t)(brow + g * 16) * 128 +
                            (uint32_t)((kb + bkoff) ^ bpx));
            #pragma unroll
            for (int mi = 0; mi < 2; ++mi) {
                mma16816(acc[mi][0], a[mi], &b[0][0]);
                mma16816(acc[mi][1], a[mi], &b[0][2]);
                mma16816(acc[mi][2], a[mi], &b[1][0]);
                mma16816(acc[mi][3], a[mi], &b[1][2]);
            }
        }
    }
#undef P_LOAD

    const int g8 = lane >> 2;
    const int t4 = lane & 3;
    #pragma unroll
    for (int ni = 0; ni < 4; ++ni) {
        const int n = wn + ni * 8 + t4 * 2;
        #pragma unroll
        for (int mi = 0; mi < 2; ++mi) {
            const int m = bm + wm + mi * 16 + g8;
            *(float2*)&g_dots[(size_t)m * 128 + n]       = make_float2(acc[mi][ni][0], acc[mi][ni][1]);
            *(float2*)&g_dots[(size_t)(m + 8) * 128 + n] = make_float2(acc[mi][ni][2], acc[mi][ni][3]);
        }
    }
}

// ---------------------------------------------------------------------------
// combine: gate+scale dots, write fp16 tail columns of g_a16 (incl. zero pad)
// ---------------------------------------------------------------------------
__global__ __launch_bounds__(256) void combine_kernel(void)
{
    int id  = blockIdx.x * 256 + threadIdx.x;  // MTOK * 128
    int m   = id >> 7;
    int col = id & 127;

    float v = 0.f;
    if (col < RTOT) {
        float d = g_dots[(size_t)m * 128 + col];
        float gmul = 1.f;
        if (col >= RANK) {
            float gt = g_dots[(size_t)m * 128 + 80 + ((col - RANK) >> 4)];
            gmul = gt > 0.f ? gt : 0.f;
        }
        v = SCALING * d * gmul;
    }
    g_a16[(size_t)m * KPAD + IN_DIM + col] = __float2half(v);
}

// ---------------------------------------------------------------------------
// Main HMMA GEMM (unchanged from R3): out = A16 @ B16^T + bias
// ---------------------------------------------------------------------------
__global__ __launch_bounds__(256, 2) void lora_gemm_hmma(
    const float* __restrict__ bias,
    float* __restrict__ out)
{
    extern __shared__ __align__(1024) char smem[];
    const uint32_t sb = smem_u32(smem);

    const int tid  = threadIdx.x;
    const int lane = tid & 31;
    const int wid  = tid >> 5;
    const int bm   = blockIdx.y * 128;
    const int bn   = blockIdx.x * 128;
    const int wm   = (wid & 1) * 64;
    const int wn   = (wid >> 1) * 32;

    float acc[4][4][4];
    #pragma unroll
    for (int mi = 0; mi < 4; ++mi)
        #pragma unroll
        for (int ni = 0; ni < 4; ++ni)
            #pragma unroll
            for (int q = 0; q < 4; ++q) acc[mi][ni][q] = 0.f;

    const char* gA = (const char*)(g_a16 + (size_t)bm * KPAD);
    const char* gB = (const char*)(g_b16 + (size_t)bn * KPAD);
    const size_t rowbytes = (size_t)KPAD * 2;

    const int crow = tid >> 3;
    const int ccol = (tid & 7) * 16;

    const int arow  = wm + (lane & 15);
    const int akoff = (lane >> 4) * 16;
    const int apx   = (arow & 7) << 4;
    const int bmat  = lane >> 3;
    const int brow  = wn + (bmat >> 1) * 8 + (lane & 7);
    const int bkoff = (bmat & 1) * 16;
    const int bpx   = (brow & 7) << 4;

#define LOAD_STAGE(s, kt)                                                      \
    {                                                                          \
        const int kb = (kt) * (BK * 2);                                        \
        _Pragma("unroll")                                                      \
        for (int i = 0; i < 4; ++i) {                                          \
            int row = crow + i * 32;                                           \
            uint32_t off = row * 128 + ccol;                                   \
            uint32_t sw  = off ^ ((off >> 3) & 0x70);                          \
            cp16(sb + (s) * STAGE_BYTES + sw, gA + (size_t)row * rowbytes + kb + ccol); \
            cp16(sb + (s) * STAGE_BYTES + ASTAGE + sw,                         \
                 gB + (size_t)row * rowbytes + kb + ccol);                     \
        }                                                                      \
        cp_commit();                                                           \
    }

    LOAD_STAGE(0, 0);
    LOAD_STAGE(1, 1);

    for (int kt = 0; kt < NKT; ++kt) {
        cp_wait1();
        __syncthreads();
        if (kt + 2 < NKT) {
            LOAD_STAGE((kt + 2) % 3, kt + 2);
        } else {
            cp_commit();
        }

        const uint32_t sa = sb + (kt % 3) * STAGE_BYTES;
        const uint32_t sB = sa + ASTAGE;

        #pragma unroll
        for (int ks = 0; ks < 4; ++ks) {
            const int kb = ks * 32;
            uint32_t a[4][4], b[2][4];
            #pragma unroll
            for (int mi = 0; mi < 4; ++mi)
                ldsm4(a[mi], sa + (uint32_t)(arow + mi * 16) * 128 +
                             (uint32_t)((kb + akoff) ^ apx));
            #pragma unroll
            for (int g = 0; g < 2; ++g)
                ldsm4(b[g], sB + (uint32_t)(brow + g * 16) * 128 +
                            (uint32_t)((kb + bkoff) ^ bpx));
            #pragma unroll
            for (int mi = 0; mi < 4; ++mi) {
                mma16816(acc[mi][0], a[mi], &b[0][0]);
                mma16816(acc[mi][1], a[mi], &b[0][2]);
                mma16816(acc[mi][2], a[mi], &b[1][0]);
                mma16816(acc[mi][3], a[mi], &b[1][2]);
            }
        }
    }
#undef LOAD_STAGE

    const int g8 = lane >> 2;
    const int t4 = lane & 3;
    #pragma unroll
    for (int ni = 0; ni < 4; ++ni) {
        const int n = bn + wn + ni * 8 + t4 * 2;
        const float2 bv = *(const float2*)&bias[n];
        #pragma unroll
        for (int mi = 0; mi < 4; ++mi) {
            const int m = bm + wm + mi * 16 + g8;
            float2 o0, o1;
            o0.x = acc[mi][ni][0] + bv.x;
            o0.y = acc[mi][ni][1] + bv.y;
            o1.x = acc[mi][ni][2] + bv.x;
            o1.y = acc[mi][ni][3] + bv.y;
            *(float2*)&out[(size_t)m * OUT_DIM + n]       = o0;
            *(float2*)&out[(size_t)(m + 8) * OUT_DIM + n] = o1;
        }
    }
}

// ---------------------------------------------------------------------------
extern "C" void kernel_launch(void* const* d_in, const int* in_sizes, int n_in,
                              void* d_out, int out_size)
{
    const float* x         = (const float*)d_in[0];
    const float* base_W    = (const float*)d_in[1];
    const float* base_b    = (const float*)d_in[2];
    const float* base_A    = (const float*)d_in[3];
    const float* base_B    = (const float*)d_in[4];
    const float* sub_wgate = (const float*)d_in[5];
    const float* sub_A     = (const float*)d_in[6];
    const float* sub_B     = (const float*)d_in[7];
    float* out = (float*)d_out;

    const int M = in_sizes[0] / IN_DIM;   // 8192 tokens

    static int attr_set = 0;
    if (!attr_set) {
        cudaFuncSetAttribute(lora_gemm_hmma,
                             cudaFuncAttributeMaxDynamicSharedMemorySize, SMEM_DYN);
        cudaFuncSetAttribute(prep_hmma,
                             cudaFuncAttributeMaxDynamicSharedMemorySize, P_SMEM);
        attr_set = 1;
    }

    conv_a_kernel<<<(M * (IN_DIM / 8)) / 256, 256>>>(x);
    conv_w_kernel<<<(128 * (IN_DIM / 8)) / 256, 256>>>(base_A, sub_A, sub_wgate);
    conv_b_kernel<<<(OUT_DIM * (KPAD / 8)) / 256, 256>>>(base_W, base_B, sub_B);

    prep_hmma<<<M / 64, 256, P_SMEM>>>();
    combine_kernel<<<(M * 128) / 256, 256>>>();

    dim3 grid(OUT_DIM / 128, M / 128);
    lora_gemm_hmma<<<grid, 256, SMEM_DYN>>>(base_b, out);
}